// round 15
// baseline (speedup 1.0000x reference)
#include <cuda_runtime.h>
#include <cuda.h>
#include <cuda_fp16.h>
#include <cstdint>

// B=16384, N=64, D=64, O=64
// softmax(others@a2 + robot@a1) == softmax(others@a2)  (robot term constant)
// out = elu( diag(1,attn) @ (h@W) )   -- attn folded into the epilogue
// TMA tiled loads (SW128, 2x 8KB panels per batch) + mbarrier completion
// replace per-lane cp.async: no L1tex queue flooding, one bar/batch.
// 128-thread dedup mapping (warp = m-tile x all 64 cols), fp16 m16n8k16,
// register-diet GEMM (split nt-halves) for 4 CTAs/SM. NBUF=3, depth 2.

#define GB 8
#define NBUF 3
#define SMEM_BYTES (NBUF * 16384 + 128 * 4 + 64 * 4 + 32 + 1024)

__device__ __forceinline__ unsigned h2u(__half2 h) {
    return *reinterpret_cast<unsigned*>(&h);
}

__device__ __forceinline__ float elu1(float x) {
    return x > 0.f ? x : (__expf(x) - 1.f);
}

__device__ __forceinline__ uint32_t smem_u32(const void* p) {
    uint32_t r;
    asm("{ .reg .u64 t; cvta.to.shared.u64 t, %1; cvt.u32.u64 %0, t; }"
        : "=r"(r) : "l"(p));
    return r;
}

__device__ __forceinline__ void tma_load_2d(uint32_t smem_addr, const void* tmap,
                                            int cx, int cy, uint32_t mbar) {
    asm volatile(
        "cp.async.bulk.tensor.2d.shared::cta.global.tile.mbarrier::complete_tx::bytes "
        "[%0], [%1, {%2, %3}], [%4];"
        :: "r"(smem_addr), "l"(tmap), "r"(cx), "r"(cy), "r"(mbar) : "memory");
}

__device__ __forceinline__ void mbar_wait(uint32_t mbar, uint32_t parity) {
    asm volatile(
        "{\n\t.reg .pred P1;\n\t"
        "WAIT_LOOP_%=:\n\t"
        "mbarrier.try_wait.parity.acquire.cta.shared::cta.b64 P1, [%0], %1, 0x989680;\n\t"
        "@P1 bra.uni WAIT_DONE_%=;\n\t"
        "bra.uni WAIT_LOOP_%=;\n\t"
        "WAIT_DONE_%=:\n\t}"
        :: "r"(mbar), "r"(parity) : "memory");
}

__global__ __launch_bounds__(128, 4)
void gat_fused_kernel(const __grid_constant__ CUtensorMap tmap,
                      const float* __restrict__ W,
                      const float* __restrict__ a,
                      float* __restrict__ out) {
    extern __shared__ char rawsm[];
    float* smf = reinterpret_cast<float*>(
        (reinterpret_cast<uintptr_t>(rawsm) + 1023) & ~(uintptr_t)1023);
    float* shbase = smf;                 // [NBUF][4096] f32, TMA SW128 panels
    float* sdots  = smf + NBUF * 4096;   // [2][64]
    float* sv2    = sdots + 128;         // [64]
    uint32_t mbar0 = smem_u32(sv2 + 64); // 3 x 8B mbarriers

    const int tid  = threadIdx.x;
    const int lane = tid & 31;
    const int warp = tid >> 5;     // 0..3 = m-tile
    const int gid  = lane >> 2;    // 0..7
    const int tig  = lane & 3;     // 0..3

    // k-chunk map: chunk(qh,tig) = (2*tig + (tig>>1)) ^ qh
    //   qh=0 -> {0,2,5,7}, qh=1 -> {1,3,4,6}:  S ∩ S^1 = ∅  (conflict-free
    //   under the SW128 row XOR for every quarter-warp phase)
    const int cbase = 2 * tig + (tig >> 1);

    // ---- B-fragments (fp16) into registers, once ----
    // col bijection: (q,tig,j) -> 32*(q>>1) + 4*chunk + j ; A/B/v2 all share it.
    // N-perm: tile nt, local n -> col (nt>>1)*16 + (n>>1)*4 + (nt&1)*2 + (n&1)
    unsigned bfr[4][8][2];
#pragma unroll
    for (int q = 0; q < 4; ++q) {
        const int kr = 32 * (q >> 1) + 4 * (cbase ^ (q & 1));
#pragma unroll
        for (int nt = 0; nt < 8; ++nt) {
            int col = (nt >> 1) * 16 + (gid >> 1) * 4 + (nt & 1) * 2 + (gid & 1);
            bfr[q][nt][0] = h2u(__floats2half2_rn(W[kr * 64 + col],
                                                  W[(kr + 1) * 64 + col]));
            bfr[q][nt][1] = h2u(__floats2half2_rn(W[(kr + 2) * 64 + col],
                                                  W[(kr + 3) * 64 + col]));
        }
    }

    // ---- v2 = W @ a2 (threads 0..63) ----
    if (tid < 64) {
        const float* a2 = a + 64;
        float s = 0.f;
#pragma unroll
        for (int o = 0; o < 64; ++o) s = fmaf(W[tid * 64 + o], a2[o], s);
        sv2[tid] = s;
    }

    // ---- init mbarriers (arrive count 1: the expect_tx arrive) ----
    if (tid == 0) {
#pragma unroll
        for (int b = 0; b < NBUF; ++b)
            asm volatile("mbarrier.init.shared.b64 [%0], 1;"
                         :: "r"(mbar0 + b * 8) : "memory");
    }
    __syncthreads();
    if (tid == 0)
        asm volatile("fence.proxy.async.shared::cta;" ::: "memory");

    const int rA = warp * 16 + gid;
    const int rB = rA + 8;
    const int rowbase0 = (int)(blockIdx.x * GB) * 64;

    // ---- issue TMA for batches 0,1 ----
    if (tid == 0) {
#pragma unroll
        for (int p = 0; p < 2; ++p) {
            uint32_t mb = mbar0 + p * 8;
            uint32_t sb = smem_u32(&shbase[p * 4096]);
            asm volatile("mbarrier.arrive.expect_tx.shared.b64 _, [%0], 16384;"
                         :: "r"(mb) : "memory");
            tma_load_2d(sb,        &tmap, 0,  rowbase0 + p * 64, mb);
            tma_load_2d(sb + 8192, &tmap, 32, rowbase0 + p * 64, mb);
        }
    }

    const size_t base = (size_t)blockIdx.x * GB * 4096;

    for (int g = 0; g < GB; ++g) {
        // ---- wait for batch g's TMA (parity = (g/NBUF)&1) ----
        mbar_wait(mbar0 + (g % NBUF) * 8, (uint32_t)((g / NBUF) & 1));

        const float* shb = &shbase[(g % NBUF) * 4096];

        // ---- per-q: swizzled LDS.128 frags, dots, convert to half2 ----
        unsigned ah0[4], ah1[4], ah2[4], ah3[4];
        float pd0 = 0.f, pd1 = 0.f;
#pragma unroll
        for (int q = 0; q < 4; ++q) {
            const int chunk = cbase ^ (q & 1);
            const int swc = chunk ^ gid;          // rA&7 == rB&7 == gid
            const float* pnl = shb + (q >> 1) * 2048;
            const float4 vA = *reinterpret_cast<const float4*>(&pnl[rA * 32 + swc * 4]);
            const float4 vB = *reinterpret_cast<const float4*>(&pnl[rB * 32 + swc * 4]);
            const float4 vv = *reinterpret_cast<const float4*>(
                                  &sv2[32 * (q >> 1) + 4 * chunk]);

            pd0 = fmaf(vA.x, vv.x, fmaf(vA.y, vv.y,
                  fmaf(vA.z, vv.z, fmaf(vA.w, vv.w, pd0))));
            pd1 = fmaf(vB.x, vv.x, fmaf(vB.y, vv.y,
                  fmaf(vB.z, vv.z, fmaf(vB.w, vv.w, pd1))));

            ah0[q] = h2u(__floats2half2_rn(vA.x, vA.y));
            ah1[q] = h2u(__floats2half2_rn(vB.x, vB.y));
            ah2[q] = h2u(__floats2half2_rn(vA.z, vA.w));
            ah3[q] = h2u(__floats2half2_rn(vB.z, vB.w));
        }

        // ---- reduce dots over tig lanes; publish (parity-buffered) ----
        pd0 += __shfl_xor_sync(0xffffffffu, pd0, 1);
        pd0 += __shfl_xor_sync(0xffffffffu, pd0, 2);
        pd1 += __shfl_xor_sync(0xffffffffu, pd1, 1);
        pd1 += __shfl_xor_sync(0xffffffffu, pd1, 2);
        float* sd = sdots + (g & 1) * 64;
        if (tig == 0) { sd[rA] = pd0; sd[rB] = pd1; }
        __syncthreads();   // the ONLY barrier: sdots ready; buf (g+2)%3 reads done

        // ---- refill buffer (g+2)%NBUF with batch g+2 ----
        if (tid == 0 && g + 2 < GB) {
            const int b = (g + 2) % NBUF;
            uint32_t mb = mbar0 + b * 8;
            uint32_t sb = smem_u32(&shbase[b * 4096]);
            asm volatile("mbarrier.arrive.expect_tx.shared.b64 _, [%0], 16384;"
                         :: "r"(mb) : "memory");
            tma_load_2d(sb,        &tmap, 0,  rowbase0 + (g + 2) * 64, mb);
            tma_load_2d(sb + 8192, &tmap, 32, rowbase0 + (g + 2) * 64, mb);
        }

        // ---- warp-local softmax over rows 1..63 ----
        float x0 = (lane >= 1) ? sd[lane] : -1e30f;
        float x1 = sd[lane + 32];
        float m = fmaxf(x0, x1);
#pragma unroll
        for (int off = 16; off; off >>= 1)
            m = fmaxf(m, __shfl_xor_sync(0xffffffffu, m, off));
        float e0s = (lane >= 1) ? __expf(x0 - m) : 0.f;
        float e1s = __expf(x1 - m);
        float s = e0s + e1s;
#pragma unroll
        for (int off = 16; off; off >>= 1)
            s += __shfl_xor_sync(0xffffffffu, s, off);
        const float inv = 1.f / s;

        const float fA = (rA == 0) ? 1.f : __expf(pd0 - m) * inv;
        const float fB = __expf(pd1 - m) * inv;   // rB >= 8, never robot

        // ---- GEMM + epilogue in two nt-halves (acc = 16 regs) ----
        float* ob = out + base + (size_t)g * 4096;
#pragma unroll
        for (int hh = 0; hh < 2; ++hh) {
            float acc[4][4];
#pragma unroll
            for (int n2 = 0; n2 < 4; ++n2)
#pragma unroll
                for (int k = 0; k < 4; ++k) acc[n2][k] = 0.f;

#pragma unroll
            for (int q = 0; q < 4; ++q) {
#pragma unroll
                for (int n2 = 0; n2 < 4; ++n2) {
                    const int nt = hh * 4 + n2;
                    asm volatile(
                        "mma.sync.aligned.m16n8k16.row.col.f32.f16.f16.f32 "
                        "{%0,%1,%2,%3}, {%4,%5,%6,%7}, {%8,%9}, {%0,%1,%2,%3};"
                        : "+f"(acc[n2][0]), "+f"(acc[n2][1]),
                          "+f"(acc[n2][2]), "+f"(acc[n2][3])
                        : "r"(ah0[q]), "r"(ah1[q]), "r"(ah2[q]), "r"(ah3[q]),
                          "r"(bfr[q][nt][0]), "r"(bfr[q][nt][1]));
                }
            }

#pragma unroll
            for (int pp = 0; pp < 2; ++pp) {
                const int col = (hh * 2 + pp) * 16 + tig * 4;
                float4 v0 = make_float4(elu1(acc[2 * pp][0] * fA),
                                        elu1(acc[2 * pp][1] * fA),
                                        elu1(acc[2 * pp + 1][0] * fA),
                                        elu1(acc[2 * pp + 1][1] * fA));
                float4 v1 = make_float4(elu1(acc[2 * pp][2] * fB),
                                        elu1(acc[2 * pp][3] * fB),
                                        elu1(acc[2 * pp + 1][2] * fB),
                                        elu1(acc[2 * pp + 1][3] * fB));
                *reinterpret_cast<float4*>(ob + rA * 64 + col) = v0;
                *reinterpret_cast<float4*>(ob + rB * 64 + col) = v1;
            }
        }
    }
}

typedef CUresult (CUDAAPI *EncodeTiledFn)(
    CUtensorMap*, CUtensorMapDataType, cuuint32_t, void*,
    const cuuint64_t*, const cuuint64_t*, const cuuint32_t*, const cuuint32_t*,
    CUtensorMapInterleave, CUtensorMapSwizzle, CUtensorMapL2promotion,
    CUtensorMapFloatOOBfill);

extern "C" void kernel_launch(void* const* d_in, const int* in_sizes, int n_in,
                              void* d_out, int out_size) {
    const float* h = (const float*)d_in[0];   // (16384, 64, 64) f32
    const float* W = (const float*)d_in[1];   // (64, 64) f32
    const float* a = (const float*)d_in[2];   // (128, 1) f32
    float* out = (float*)d_out;               // (16384, 64, 64) f32

    // Build the TMA descriptor (driver entry via cudart: no -lcuda needed).
    void* fn = nullptr;
    cudaDriverEntryPointQueryResult qr;
    cudaGetDriverEntryPointByVersion("cuTensorMapEncodeTiled", &fn, 12000,
                                     cudaEnableDefault, &qr);
    CUtensorMap tmap;
    {
        EncodeTiledFn enc = (EncodeTiledFn)fn;
        cuuint64_t dims[2]    = {64, (cuuint64_t)16384 * 64};   // cols, rows
        cuuint64_t strides[1] = {256};                          // row stride (bytes)
        cuuint32_t box[2]     = {32, 64};   // 32 f32 = 128B = SW128 atom width
        cuuint32_t estr[2]    = {1, 1};
        enc(&tmap, CU_TENSOR_MAP_DATA_TYPE_FLOAT32, 2, (void*)h,
            dims, strides, box, estr,
            CU_TENSOR_MAP_INTERLEAVE_NONE, CU_TENSOR_MAP_SWIZZLE_128B,
            CU_TENSOR_MAP_L2_PROMOTION_L2_128B,
            CU_TENSOR_MAP_FLOAT_OOB_FILL_NONE);
    }

    cudaFuncSetAttribute(gat_fused_kernel,
                         cudaFuncAttributeMaxDynamicSharedMemorySize, SMEM_BYTES);
    gat_fused_kernel<<<16384 / GB, 128, SMEM_BYTES>>>(tmap, W, a, out);
}

// round 16
// speedup vs baseline: 1.1709x; 1.1709x over previous
#include <cuda_runtime.h>
#include <cuda_fp16.h>
#include <cstdint>

// B=16384, N=64, D=64, O=64
// softmax(others@a2 + robot@a1) == softmax(others@a2)  (robot term constant)
// out = elu( diag(1,attn) @ (h@W) )   -- attn folded into the epilogue
// R10 structure (best): 128-thread dedup mapping (warp = m-tile x all 64
// cols), fp16 m16n8k16, B-frags + v2 in registers, triple-buffered h smem,
// cp.async prefetch depth 2. R16 deltas: GB=16 (prologue/wave amortization),
// __stcs streaming stores for the write-once output.

#define GB 16     // batches per CTA
#define HS 80     // h smem row stride (floats): conflict-free float4 phases
#define NBUF 3

#define SMEM_FLOATS (NBUF * 64 * HS + 2 * 64 + 64)

__device__ __forceinline__ unsigned h2u(__half2 h) {
    return *reinterpret_cast<unsigned*>(&h);
}

__device__ __forceinline__ float elu1(float x) {
    return x > 0.f ? x : (__expf(x) - 1.f);
}

__device__ __forceinline__ void cp_async16(uint32_t saddr, const void* gptr) {
    asm volatile("cp.async.cg.shared.global [%0], [%1], 16;\n"
                 :: "r"(saddr), "l"(gptr));
}

__global__ __launch_bounds__(128)
void gat_fused_kernel(const float* __restrict__ h,
                      const float* __restrict__ W,
                      const float* __restrict__ a,
                      float* __restrict__ out) {
    extern __shared__ float smem[];
    float* shbase = smem;                       // [NBUF][64*HS]
    float* sdots  = smem + NBUF * 64 * HS;      // [2][64]
    float* sv2    = sdots + 128;                // [64], 16B-aligned

    const int tid  = threadIdx.x;
    const int lane = tid & 31;
    const int warp = tid >> 5;     // 0..3 = m-tile
    const int gid  = lane >> 2;    // 0..7
    const int tig  = lane & 3;     // 0..3

    // ---- B-fragments (fp16) into registers, once ----
    // K-perm within slab q: actual col 16q+4t+j <-> mma-k {2t,2t+1,2t+8,2t+9}
    // N-perm: tile nt, local n -> col (nt>>1)*16 + (n>>1)*4 + (nt&1)*2 + (n&1)
    unsigned bfr[4][8][2];
#pragma unroll
    for (int q = 0; q < 4; ++q) {
        const int kr = 16 * q + 4 * tig;
#pragma unroll
        for (int nt = 0; nt < 8; ++nt) {
            int col = (nt >> 1) * 16 + (gid >> 1) * 4 + (nt & 1) * 2 + (gid & 1);
            bfr[q][nt][0] = h2u(__floats2half2_rn(W[kr * 64 + col],
                                                  W[(kr + 1) * 64 + col]));
            bfr[q][nt][1] = h2u(__floats2half2_rn(W[(kr + 2) * 64 + col],
                                                  W[(kr + 3) * 64 + col]));
        }
    }

    // ---- v2 = W @ a2 (threads 0..63) ----
    if (tid < 64) {
        const float* a2 = a + 64;
        float s = 0.f;
#pragma unroll
        for (int o = 0; o < 64; ++o) s = fmaf(W[tid * 64 + o], a2[o], s);
        sv2[tid] = s;
    }
    __syncthreads();

    // v2 values this thread needs (cols 16q+4tig..+3), loop-invariant
    float4 vv[4];
#pragma unroll
    for (int q = 0; q < 4; ++q)
        vv[q] = *reinterpret_cast<const float4*>(&sv2[16 * q + 4 * tig]);

    const size_t base = (size_t)blockIdx.x * GB * 4096;

    // ---- prefetch batches 0,1 (two commit groups) ----
#pragma unroll
    for (int p = 0; p < 2; ++p) {
        const float* hb = h + base + (size_t)p * 4096;
        uint32_t sb = (uint32_t)__cvta_generic_to_shared(&shbase[p * 64 * HS]);
#pragma unroll
        for (int c = tid; c < 1024; c += 128) {
            int row = c >> 4, q = c & 15;
            cp_async16(sb + (row * HS + q * 4) * 4, hb + c * 4);
        }
        asm volatile("cp.async.commit_group;\n");
    }

    const int rA = warp * 16 + gid;   // this thread's two rows
    const int rB = rA + 8;

    for (int g = 0; g < GB; ++g) {
        // complete batch g's copy (leave the newer group in flight)
        if (g + 1 < GB)
            asm volatile("cp.async.wait_group 1;\n");
        else
            asm volatile("cp.async.wait_group 0;\n");
        __syncthreads();   // bar A: buffer g visible; buffer (g+2)%3 free

        // ---- prefetch batch g+2 into buffer (g+2)%NBUF ----
        if (g + 2 < GB) {
            const float* hb = h + base + (size_t)(g + 2) * 4096;
            uint32_t sb = (uint32_t)__cvta_generic_to_shared(
                              &shbase[((g + 2) % NBUF) * 64 * HS]);
#pragma unroll
            for (int c = tid; c < 1024; c += 128) {
                int row = c >> 4, q = c & 15;
                cp_async16(sb + (row * HS + q * 4) * 4, hb + c * 4);
            }
            asm volatile("cp.async.commit_group;\n");
        }

        const float* shb = &shbase[(g % NBUF) * 64 * HS];

        // ---- load all A fragments up front (8x LDS.128, max MLP) ----
        float4 fAr[4], fBr[4];
#pragma unroll
        for (int q = 0; q < 4; ++q) {
            const int cb = 16 * q + 4 * tig;
            fAr[q] = *reinterpret_cast<const float4*>(&shb[rA * HS + cb]);
            fBr[q] = *reinterpret_cast<const float4*>(&shb[rB * HS + cb]);
        }

        // ---- fp32 dot partials ----
        float pd0 = 0.f, pd1 = 0.f;
#pragma unroll
        for (int q = 0; q < 4; ++q) {
            pd0 = fmaf(fAr[q].x, vv[q].x, fmaf(fAr[q].y, vv[q].y,
                  fmaf(fAr[q].z, vv[q].z, fmaf(fAr[q].w, vv[q].w, pd0))));
            pd1 = fmaf(fBr[q].x, vv[q].x, fmaf(fBr[q].y, vv[q].y,
                  fmaf(fBr[q].z, vv[q].z, fmaf(fBr[q].w, vv[q].w, pd1))));
        }

        // ---- GEMM (fp16, unscaled, 8 n-tiles) ----
        float acc[8][4];
#pragma unroll
        for (int nt = 0; nt < 8; ++nt)
#pragma unroll
            for (int k = 0; k < 4; ++k) acc[nt][k] = 0.f;

#pragma unroll
        for (int q = 0; q < 4; ++q) {
            unsigned a0 = h2u(__floats2half2_rn(fAr[q].x, fAr[q].y));
            unsigned a1 = h2u(__floats2half2_rn(fBr[q].x, fBr[q].y));
            unsigned a2 = h2u(__floats2half2_rn(fAr[q].z, fAr[q].w));
            unsigned a3 = h2u(__floats2half2_rn(fBr[q].z, fBr[q].w));
#pragma unroll
            for (int nt = 0; nt < 8; ++nt) {
                asm volatile(
                    "mma.sync.aligned.m16n8k16.row.col.f32.f16.f16.f32 "
                    "{%0,%1,%2,%3}, {%4,%5,%6,%7}, {%8,%9}, {%0,%1,%2,%3};"
                    : "+f"(acc[nt][0]), "+f"(acc[nt][1]),
                      "+f"(acc[nt][2]), "+f"(acc[nt][3])
                    : "r"(a0), "r"(a1), "r"(a2), "r"(a3),
                      "r"(bfr[q][nt][0]), "r"(bfr[q][nt][1]));
            }
        }

        // ---- reduce dots over tig lanes; publish (parity-buffered) ----
        pd0 += __shfl_xor_sync(0xffffffffu, pd0, 1);
        pd0 += __shfl_xor_sync(0xffffffffu, pd0, 2);
        pd1 += __shfl_xor_sync(0xffffffffu, pd1, 1);
        pd1 += __shfl_xor_sync(0xffffffffu, pd1, 2);
        float* sd = sdots + (g & 1) * 64;
        if (tig == 0) {
            sd[rA] = pd0;
            sd[rB] = pd1;
        }
        __syncthreads();   // bar B: sdots complete

        // ---- warp-local softmax over rows 1..63 ----
        float x0 = (lane >= 1) ? sd[lane] : -1e30f;
        float x1 = sd[lane + 32];
        float m = fmaxf(x0, x1);
#pragma unroll
        for (int off = 16; off; off >>= 1)
            m = fmaxf(m, __shfl_xor_sync(0xffffffffu, m, off));
        float e0s = (lane >= 1) ? __expf(x0 - m) : 0.f;
        float e1s = __expf(x1 - m);
        float s = e0s + e1s;
#pragma unroll
        for (int off = 16; off; off >>= 1)
            s += __shfl_xor_sync(0xffffffffu, s, off);
        const float inv = 1.f / s;

        const float fA = (rA == 0) ? 1.f : __expf(pd0 - m) * inv;
        const float fB = __expf(pd1 - m) * inv;   // rB >= 8, never robot

        // ---- epilogue: scale, elu, 8x streaming STG.128 ----
        float* ob = out + base + (size_t)g * 4096;
#pragma unroll
        for (int p = 0; p < 4; ++p) {
            const int col = p * 16 + tig * 4;
            float4 v0 = make_float4(elu1(acc[2 * p][0] * fA),
                                    elu1(acc[2 * p][1] * fA),
                                    elu1(acc[2 * p + 1][0] * fA),
                                    elu1(acc[2 * p + 1][1] * fA));
            float4 v1 = make_float4(elu1(acc[2 * p][2] * fB),
                                    elu1(acc[2 * p][3] * fB),
                                    elu1(acc[2 * p + 1][2] * fB),
                                    elu1(acc[2 * p + 1][3] * fB));
            __stcs(reinterpret_cast<float4*>(ob + rA * 64 + col), v0);
            __stcs(reinterpret_cast<float4*>(ob + rB * 64 + col), v1);
        }
    }
}

extern "C" void kernel_launch(void* const* d_in, const int* in_sizes, int n_in,
                              void* d_out, int out_size) {
    const float* h = (const float*)d_in[0];   // (16384, 64, 64) f32
    const float* W = (const float*)d_in[1];   // (64, 64) f32
    const float* a = (const float*)d_in[2];   // (128, 1) f32
    float* out = (float*)d_out;               // (16384, 64, 64) f32

    const int smem_bytes = SMEM_FLOATS * sizeof(float);   // ~62 KB
    cudaFuncSetAttribute(gat_fused_kernel,
                         cudaFuncAttributeMaxDynamicSharedMemorySize, smem_bytes);
    gat_fused_kernel<<<16384 / GB, 128, smem_bytes>>>(h, W, a, out);
}

// round 17
// speedup vs baseline: 1.4131x; 1.2069x over previous
#include <cuda_runtime.h>
#include <cuda_fp16.h>
#include <cstdint>

// B=16384, N=64, D=64, O=64
// softmax(others@a2 + robot@a1) == softmax(others@a2)  (robot term constant)
// out = elu( diag(1,attn) @ (h@W) )   -- attn folded into the epilogue
// R16 champion body with a PERSISTENT-SHAPED grid: 444 CTAs = 3/SM x 148 SMs,
// each processing a contiguous run of 36-37 batches (no wave transitions, no
// tail quantization). 128-thread dedup mapping, fp16 m16n8k16, B-frags + v2
// in registers, triple-buffered cp.async depth 2, __stcs streaming stores.

#define HS 80     // h smem row stride (floats): conflict-free float4 phases
#define NBUF 3
#define GRID 444          // 3 CTAs/SM x 148 SMs
#define NB_BASE 36        // 16384 = 444*36 + 400
#define NB_EXTRA 400

#define SMEM_FLOATS (NBUF * 64 * HS + 2 * 64 + 64)

__device__ __forceinline__ unsigned h2u(__half2 h) {
    return *reinterpret_cast<unsigned*>(&h);
}

__device__ __forceinline__ float elu1(float x) {
    return x > 0.f ? x : (__expf(x) - 1.f);
}

__device__ __forceinline__ void cp_async16(uint32_t saddr, const void* gptr) {
    asm volatile("cp.async.cg.shared.global [%0], [%1], 16;\n"
                 :: "r"(saddr), "l"(gptr));
}

__global__ __launch_bounds__(128)
void gat_fused_kernel(const float* __restrict__ h,
                      const float* __restrict__ W,
                      const float* __restrict__ a,
                      float* __restrict__ out) {
    extern __shared__ float smem[];
    float* shbase = smem;                       // [NBUF][64*HS]
    float* sdots  = smem + NBUF * 64 * HS;      // [2][64]
    float* sv2    = sdots + 128;                // [64], 16B-aligned

    const int tid  = threadIdx.x;
    const int lane = tid & 31;
    const int warp = tid >> 5;     // 0..3 = m-tile
    const int gid  = lane >> 2;    // 0..7
    const int tig  = lane & 3;     // 0..3

    // ---- per-CTA batch range (balanced split of 16384) ----
    const int cta = blockIdx.x;
    const int nb = NB_BASE + (cta < NB_EXTRA ? 1 : 0);
    const size_t b0 = (size_t)cta * NB_BASE + (cta < NB_EXTRA ? cta : NB_EXTRA);

    // ---- B-fragments (fp16) into registers, once ----
    // K-perm within slab q: actual col 16q+4t+j <-> mma-k {2t,2t+1,2t+8,2t+9}
    // N-perm: tile nt, local n -> col (nt>>1)*16 + (n>>1)*4 + (nt&1)*2 + (n&1)
    unsigned bfr[4][8][2];
#pragma unroll
    for (int q = 0; q < 4; ++q) {
        const int kr = 16 * q + 4 * tig;
#pragma unroll
        for (int nt = 0; nt < 8; ++nt) {
            int col = (nt >> 1) * 16 + (gid >> 1) * 4 + (nt & 1) * 2 + (gid & 1);
            bfr[q][nt][0] = h2u(__floats2half2_rn(W[kr * 64 + col],
                                                  W[(kr + 1) * 64 + col]));
            bfr[q][nt][1] = h2u(__floats2half2_rn(W[(kr + 2) * 64 + col],
                                                  W[(kr + 3) * 64 + col]));
        }
    }

    // ---- v2 = W @ a2 (threads 0..63) ----
    if (tid < 64) {
        const float* a2 = a + 64;
        float s = 0.f;
#pragma unroll
        for (int o = 0; o < 64; ++o) s = fmaf(W[tid * 64 + o], a2[o], s);
        sv2[tid] = s;
    }
    __syncthreads();

    // v2 values this thread needs (cols 16q+4tig..+3), loop-invariant
    float4 vv[4];
#pragma unroll
    for (int q = 0; q < 4; ++q)
        vv[q] = *reinterpret_cast<const float4*>(&sv2[16 * q + 4 * tig]);

    const size_t base = b0 * 4096;

    // ---- prefetch batches 0,1 (two commit groups) ----
#pragma unroll
    for (int p = 0; p < 2; ++p) {
        const float* hb = h + base + (size_t)p * 4096;
        uint32_t sb = (uint32_t)__cvta_generic_to_shared(&shbase[p * 64 * HS]);
#pragma unroll
        for (int c = tid; c < 1024; c += 128) {
            int row = c >> 4, q = c & 15;
            cp_async16(sb + (row * HS + q * 4) * 4, hb + c * 4);
        }
        asm volatile("cp.async.commit_group;\n");
    }

    const int rA = warp * 16 + gid;   // this thread's two rows
    const int rB = rA + 8;

    for (int g = 0; g < nb; ++g) {
        // complete batch g's copy (leave the newer group in flight)
        if (g + 1 < nb)
            asm volatile("cp.async.wait_group 1;\n");
        else
            asm volatile("cp.async.wait_group 0;\n");
        __syncthreads();   // bar A: buffer g visible; buffer (g+2)%3 free

        // ---- prefetch batch g+2 into buffer (g+2)%NBUF ----
        if (g + 2 < nb) {
            const float* hb = h + base + (size_t)(g + 2) * 4096;
            uint32_t sb = (uint32_t)__cvta_generic_to_shared(
                              &shbase[((g + 2) % NBUF) * 64 * HS]);
#pragma unroll
            for (int c = tid; c < 1024; c += 128) {
                int row = c >> 4, q = c & 15;
                cp_async16(sb + (row * HS + q * 4) * 4, hb + c * 4);
            }
            asm volatile("cp.async.commit_group;\n");
        }

        const float* shb = &shbase[(g % NBUF) * 64 * HS];

        // ---- load all A fragments up front (8x LDS.128, max MLP) ----
        float4 fAr[4], fBr[4];
#pragma unroll
        for (int q = 0; q < 4; ++q) {
            const int cb = 16 * q + 4 * tig;
            fAr[q] = *reinterpret_cast<const float4*>(&shb[rA * HS + cb]);
            fBr[q] = *reinterpret_cast<const float4*>(&shb[rB * HS + cb]);
        }

        // ---- fp32 dot partials ----
        float pd0 = 0.f, pd1 = 0.f;
#pragma unroll
        for (int q = 0; q < 4; ++q) {
            pd0 = fmaf(fAr[q].x, vv[q].x, fmaf(fAr[q].y, vv[q].y,
                  fmaf(fAr[q].z, vv[q].z, fmaf(fAr[q].w, vv[q].w, pd0))));
            pd1 = fmaf(fBr[q].x, vv[q].x, fmaf(fBr[q].y, vv[q].y,
                  fmaf(fBr[q].z, vv[q].z, fmaf(fBr[q].w, vv[q].w, pd1))));
        }

        // ---- GEMM (fp16, unscaled, 8 n-tiles) ----
        float acc[8][4];
#pragma unroll
        for (int nt = 0; nt < 8; ++nt)
#pragma unroll
            for (int k = 0; k < 4; ++k) acc[nt][k] = 0.f;

#pragma unroll
        for (int q = 0; q < 4; ++q) {
            unsigned a0 = h2u(__floats2half2_rn(fAr[q].x, fAr[q].y));
            unsigned a1 = h2u(__floats2half2_rn(fBr[q].x, fBr[q].y));
            unsigned a2 = h2u(__floats2half2_rn(fAr[q].z, fAr[q].w));
            unsigned a3 = h2u(__floats2half2_rn(fBr[q].z, fBr[q].w));
#pragma unroll
            for (int nt = 0; nt < 8; ++nt) {
                asm volatile(
                    "mma.sync.aligned.m16n8k16.row.col.f32.f16.f16.f32 "
                    "{%0,%1,%2,%3}, {%4,%5,%6,%7}, {%8,%9}, {%0,%1,%2,%3};"
                    : "+f"(acc[nt][0]), "+f"(acc[nt][1]),
                      "+f"(acc[nt][2]), "+f"(acc[nt][3])
                    : "r"(a0), "r"(a1), "r"(a2), "r"(a3),
                      "r"(bfr[q][nt][0]), "r"(bfr[q][nt][1]));
            }
        }

        // ---- reduce dots over tig lanes; publish (parity-buffered) ----
        pd0 += __shfl_xor_sync(0xffffffffu, pd0, 1);
        pd0 += __shfl_xor_sync(0xffffffffu, pd0, 2);
        pd1 += __shfl_xor_sync(0xffffffffu, pd1, 1);
        pd1 += __shfl_xor_sync(0xffffffffu, pd1, 2);
        float* sd = sdots + (g & 1) * 64;
        if (tig == 0) {
            sd[rA] = pd0;
            sd[rB] = pd1;
        }
        __syncthreads();   // bar B: sdots complete

        // ---- warp-local softmax over rows 1..63 ----
        float x0 = (lane >= 1) ? sd[lane] : -1e30f;
        float x1 = sd[lane + 32];
        float m = fmaxf(x0, x1);
#pragma unroll
        for (int off = 16; off; off >>= 1)
            m = fmaxf(m, __shfl_xor_sync(0xffffffffu, m, off));
        float e0s = (lane >= 1) ? __expf(x0 - m) : 0.f;
        float e1s = __expf(x1 - m);
        float s = e0s + e1s;
#pragma unroll
        for (int off = 16; off; off >>= 1)
            s += __shfl_xor_sync(0xffffffffu, s, off);
        const float inv = 1.f / s;

        const float fA = (rA == 0) ? 1.f : __expf(pd0 - m) * inv;
        const float fB = __expf(pd1 - m) * inv;   // rB >= 8, never robot

        // ---- epilogue: scale, elu, 8x streaming STG.128 ----
        float* ob = out + base + (size_t)g * 4096;
#pragma unroll
        for (int p = 0; p < 4; ++p) {
            const int col = p * 16 + tig * 4;
            float4 v0 = make_float4(elu1(acc[2 * p][0] * fA),
                                    elu1(acc[2 * p][1] * fA),
                                    elu1(acc[2 * p + 1][0] * fA),
                                    elu1(acc[2 * p + 1][1] * fA));
            float4 v1 = make_float4(elu1(acc[2 * p][2] * fB),
                                    elu1(acc[2 * p][3] * fB),
                                    elu1(acc[2 * p + 1][2] * fB),
                                    elu1(acc[2 * p + 1][3] * fB));
            __stcs(reinterpret_cast<float4*>(ob + rA * 64 + col), v0);
            __stcs(reinterpret_cast<float4*>(ob + rB * 64 + col), v1);
        }
    }
}

extern "C" void kernel_launch(void* const* d_in, const int* in_sizes, int n_in,
                              void* d_out, int out_size) {
    const float* h = (const float*)d_in[0];   // (16384, 64, 64) f32
    const float* W = (const float*)d_in[1];   // (64, 64) f32
    const float* a = (const float*)d_in[2];   // (128, 1) f32
    float* out = (float*)d_out;               // (16384, 64, 64) f32

    const int smem_bytes = SMEM_FLOATS * sizeof(float);   // ~62 KB
    cudaFuncSetAttribute(gat_fused_kernel,
                         cudaFuncAttributeMaxDynamicSharedMemorySize, smem_bytes);
    gat_fused_kernel<<<GRID, 128, smem_bytes>>>(h, W, a, out);
}